// round 5
// baseline (speedup 1.0000x reference)
#include <cuda_runtime.h>
#include <cuda_bf16.h>
#include <cstdint>
#include <type_traits>

// ---------------------------------------------------------------------------
// MemoryBank fused pipeline, GB300 sm_103a, round 5 (resubmission — broker
// timeout rounds 0-4; design frozen until first real profile lands).
// bf16 mma.sync GEMMs (fp32 accum) + fused epilogues + warp-per-track attention.
// ---------------------------------------------------------------------------

#define DIM 256            // D
#define LMEM 4             // memory bank length

// Scratch partition (bytes), all 16B aligned:
//  g_q   bf16 [N,256]        51,200,000
//  g_kv  bf16 [N*4,512]     409,600,000
//  g_ctx bf16 [N,256]        51,200,000
//  g_h   bf16 [N,256]        51,200,000
//  g_y   f32  [N,256]       102,400,000
//  g_e   f32  [N,256]       102,400,000
//  g_sv  f32  [N,256]       102,400,000
#define OFF_Q   0ull
#define OFF_KV  51200000ull
#define OFF_CTX 460800000ull
#define OFF_H   512000000ull
#define OFF_Y   563200000ull
#define OFF_E   665600000ull
#define OFF_SV  768000000ull
#define SCRATCH_BYTES 870400000ull

__device__ __align__(128) unsigned char g_scratch[SCRATCH_BYTES];

// ---------------------------------------------------------------------------
// bf16 m16n8k16 mma
// ---------------------------------------------------------------------------
__device__ __forceinline__ void mma_bf16(float (&d)[4], const unsigned (&a)[4],
                                         const unsigned (&b)[2]) {
    asm volatile(
        "mma.sync.aligned.m16n8k16.row.col.f32.bf16.bf16.f32 "
        "{%0,%1,%2,%3}, {%4,%5,%6,%7}, {%8,%9}, {%0,%1,%2,%3};\n"
        : "+f"(d[0]), "+f"(d[1]), "+f"(d[2]), "+f"(d[3])
        : "r"(a[0]), "r"(a[1]), "r"(a[2]), "r"(a[3]), "r"(b[0]), "r"(b[1]));
}

// ---------------------------------------------------------------------------
// Generic GEMM: C[M, ldc-slice] = A[M,256] @ W[Nc,256]^T + bias (+epilogue)
// BM=128, BN=128, BK=32; 256 threads; warp grid 2(m) x 4(n), warp tile 64x32.
// EPI: 0 = bias, 1 = bias+relu, 2 = bias + residual (resid is [M,256] f32).
// ---------------------------------------------------------------------------
#define BM 128
#define BN 128
#define BK 32
#define SPAD 40   // smem row pitch (bf16 elems): conflict-free for frag loads

template <typename TA, int EPI, typename TO>
__global__ __launch_bounds__(256, 2)
void gemm_k(const TA* __restrict__ A, const float* __restrict__ W,
            const float* __restrict__ bias, const float* __restrict__ resid,
            TO* __restrict__ C, int M, int ldc)
{
    __shared__ __nv_bfloat16 sA[BM * SPAD];
    __shared__ __nv_bfloat16 sB[BN * SPAD];

    const int tid  = threadIdx.x;
    const int bm   = blockIdx.y * BM;
    const int bn   = blockIdx.x * BN;
    const int w    = tid >> 5, lane = tid & 31;
    const int wm   = w >> 2,  wn   = w & 3;
    const int g    = lane >> 2, t  = lane & 3;

    float acc[4][4][4];
    #pragma unroll
    for (int i = 0; i < 4; i++)
        #pragma unroll
        for (int j = 0; j < 4; j++)
            #pragma unroll
            for (int k = 0; k < 4; k++) acc[i][j][k] = 0.f;

    for (int k0 = 0; k0 < DIM; k0 += BK) {
        // ---- load A tile (convert to bf16 if fp32) ----
        if constexpr (std::is_same<TA, float>::value) {
            #pragma unroll
            for (int i = 0; i < 4; i++) {
                int idx = tid + i * 256;
                int r = idx >> 3, c4 = (idx & 7) * 4;
                float4 v = make_float4(0.f, 0.f, 0.f, 0.f);
                if (bm + r < M)
                    v = *(const float4*)&A[(size_t)(bm + r) * DIM + k0 + c4];
                __nv_bfloat162* dst = (__nv_bfloat162*)&sA[r * SPAD + c4];
                dst[0] = __floats2bfloat162_rn(v.x, v.y);
                dst[1] = __floats2bfloat162_rn(v.z, v.w);
            }
        } else {
            #pragma unroll
            for (int i = 0; i < 2; i++) {
                int idx = tid + i * 256;
                int r = idx >> 2, c8 = (idx & 3) * 8;
                uint4 v = make_uint4(0u, 0u, 0u, 0u);
                if (bm + r < M)
                    v = *(const uint4*)&A[(size_t)(bm + r) * DIM + k0 + c8];
                *(uint4*)&sA[r * SPAD + c8] = v;
            }
        }
        // ---- load W tile (always fp32, rows are output channels) ----
        #pragma unroll
        for (int i = 0; i < 4; i++) {
            int idx = tid + i * 256;
            int r = idx >> 3, c4 = (idx & 7) * 4;
            float4 v = *(const float4*)&W[(size_t)(bn + r) * DIM + k0 + c4];
            __nv_bfloat162* dst = (__nv_bfloat162*)&sB[r * SPAD + c4];
            dst[0] = __floats2bfloat162_rn(v.x, v.y);
            dst[1] = __floats2bfloat162_rn(v.z, v.w);
        }
        __syncthreads();

        #pragma unroll
        for (int km = 0; km < 2; km++) {
            const int kc = km * 16;
            unsigned af[4][4], bf[4][2];
            #pragma unroll
            for (int im = 0; im < 4; im++) {
                int r = wm * 64 + im * 16 + g;
                af[im][0] = *(const unsigned*)&sA[r * SPAD + kc + 2 * t];
                af[im][1] = *(const unsigned*)&sA[(r + 8) * SPAD + kc + 2 * t];
                af[im][2] = *(const unsigned*)&sA[r * SPAD + kc + 8 + 2 * t];
                af[im][3] = *(const unsigned*)&sA[(r + 8) * SPAD + kc + 8 + 2 * t];
            }
            #pragma unroll
            for (int jn = 0; jn < 4; jn++) {
                int nc = wn * 32 + jn * 8 + g;
                bf[jn][0] = *(const unsigned*)&sB[nc * SPAD + kc + 2 * t];
                bf[jn][1] = *(const unsigned*)&sB[nc * SPAD + kc + 8 + 2 * t];
            }
            #pragma unroll
            for (int im = 0; im < 4; im++)
                #pragma unroll
                for (int jn = 0; jn < 4; jn++)
                    mma_bf16(acc[im][jn], af[im], bf[jn]);
        }
        __syncthreads();
    }

    // ---- epilogue ----
    #pragma unroll
    for (int im = 0; im < 4; im++) {
        int rbase = bm + wm * 64 + im * 16 + g;
        #pragma unroll
        for (int jn = 0; jn < 4; jn++) {
            int c0 = bn + wn * 32 + jn * 8 + 2 * t;
            float b0 = bias[c0], b1 = bias[c0 + 1];
            #pragma unroll
            for (int half = 0; half < 2; half++) {
                int r = rbase + half * 8;
                if (r >= M) continue;
                float x0 = acc[im][jn][half * 2 + 0] + b0;
                float x1 = acc[im][jn][half * 2 + 1] + b1;
                if (EPI == 1) { x0 = fmaxf(x0, 0.f); x1 = fmaxf(x1, 0.f); }
                if (EPI == 2) {
                    const float* rp = resid + (size_t)r * DIM + c0;
                    x0 += rp[0]; x1 += rp[1];
                }
                if constexpr (std::is_same<TO, float>::value) {
                    *(float2*)&C[(size_t)r * ldc + c0] = make_float2(x0, x1);
                } else {
                    *(__nv_bfloat162*)&C[(size_t)r * ldc + c0] =
                        __floats2bfloat162_rn(x0, x1);
                }
            }
        }
    }
}

// ---------------------------------------------------------------------------
// Attention: one warp per track. lane -> (h = lane/4, l = lane%4).
// logits over L=4 slots per head, softmax within 4-lane groups.
// ---------------------------------------------------------------------------
__global__ __launch_bounds__(256)
void attn_k(const __nv_bfloat16* __restrict__ q, const __nv_bfloat16* __restrict__ kv,
            const unsigned* __restrict__ mask, __nv_bfloat16* __restrict__ ctx, int n)
{
    int w = blockIdx.x * 8 + (threadIdx.x >> 5);
    if (w >= n) return;
    int lane = threadIdx.x & 31;
    int h = lane >> 2, l = lane & 3;

    bool valid = (mask[(size_t)w * 4 + 3] == 0u);
    bool pad   = valid && (mask[(size_t)w * 4 + l] != 0u);

    const __nv_bfloat162* qp = (const __nv_bfloat162*)(q + (size_t)w * DIM + h * 32);
    const __nv_bfloat162* kp = (const __nv_bfloat162*)(kv + ((size_t)w * 4 + l) * 512 + h * 32);
    float dot = 0.f;
    #pragma unroll
    for (int i = 0; i < 16; i++) {
        float2 qf = __bfloat1622float2(qp[i]);
        float2 kf = __bfloat1622float2(kp[i]);
        dot += qf.x * kf.x + qf.y * kf.y;
    }
    float logit = dot * 0.17677669529663687f;   // 1/sqrt(32)
    if (pad) logit = -1e9f;

    float m = logit;
    m = fmaxf(m, __shfl_xor_sync(0xffffffffu, m, 1));
    m = fmaxf(m, __shfl_xor_sync(0xffffffffu, m, 2));
    float p = __expf(logit - m);
    float s = p;
    s += __shfl_xor_sync(0xffffffffu, s, 1);
    s += __shfl_xor_sync(0xffffffffu, s, 2);
    float attn = p / s;

    const __nv_bfloat162* vp = (const __nv_bfloat162*)(kv + ((size_t)w * 4 + l) * 512 + 256 + h * 32);
    float c[32];
    #pragma unroll
    for (int i = 0; i < 16; i++) {
        float2 vf = __bfloat1622float2(vp[i]);
        c[2 * i]     = attn * vf.x;
        c[2 * i + 1] = attn * vf.y;
    }
    #pragma unroll
    for (int i = 0; i < 32; i++) {
        c[i] += __shfl_xor_sync(0xffffffffu, c[i], 1);
        c[i] += __shfl_xor_sync(0xffffffffu, c[i], 2);
    }
    // lane with slot l writes dims [l*8, l*8+8)
    __nv_bfloat162* op = (__nv_bfloat162*)(ctx + (size_t)w * DIM + h * 32 + l * 8);
    #pragma unroll
    for (int j = 0; j < 4; j++)
        op[j] = __floats2bfloat162_rn(c[l * 8 + 2 * j], c[l * 8 + 2 * j + 1]);
}

// ---------------------------------------------------------------------------
// LayerNorm helpers (one warp per row of 256)
// ---------------------------------------------------------------------------
__device__ __forceinline__ float warp_sum(float v) {
    #pragma unroll
    for (int o = 16; o; o >>= 1) v += __shfl_xor_sync(0xffffffffu, v, o);
    return v;
}

__global__ __launch_bounds__(256)
void ln_k(const float* __restrict__ x, const float* __restrict__ gam,
          const float* __restrict__ bet, float* __restrict__ out, int n)
{
    int w = blockIdx.x * 8 + (threadIdx.x >> 5);
    if (w >= n) return;
    int lane = threadIdx.x & 31;
    const float4* xp = (const float4*)(x + (size_t)w * DIM);
    float4 v0 = xp[lane], v1 = xp[lane + 32];
    float s = v0.x + v0.y + v0.z + v0.w + v1.x + v1.y + v1.z + v1.w;
    float mu = warp_sum(s) * (1.f / DIM);
    float d0x = v0.x - mu, d0y = v0.y - mu, d0z = v0.z - mu, d0w = v0.w - mu;
    float d1x = v1.x - mu, d1y = v1.y - mu, d1z = v1.z - mu, d1w = v1.w - mu;
    float q = d0x*d0x + d0y*d0y + d0z*d0z + d0w*d0w + d1x*d1x + d1y*d1y + d1z*d1z + d1w*d1w;
    float inv = rsqrtf(warp_sum(q) * (1.f / DIM) + 1e-5f);
    const float4* gp = (const float4*)gam;
    const float4* bp = (const float4*)bet;
    float4 ga = gp[lane], gb = gp[lane + 32], ba = bp[lane], bb = bp[lane + 32];
    float4 o0 = make_float4(d0x*inv*ga.x + ba.x, d0y*inv*ga.y + ba.y,
                            d0z*inv*ga.z + ba.z, d0w*inv*ga.w + ba.w);
    float4 o1 = make_float4(d1x*inv*gb.x + bb.x, d1y*inv*gb.y + bb.y,
                            d1z*inv*gb.z + bb.z, d1w*inv*gb.w + bb.w);
    float4* dst = (float4*)(out + (size_t)w * DIM);
    dst[lane] = o0; dst[lane + 32] = o1;
}

__global__ __launch_bounds__(256)
void ln2sel_k(const float* __restrict__ x, const float* __restrict__ gam,
              const float* __restrict__ bet, const unsigned* __restrict__ mask,
              const float* __restrict__ x0, float* __restrict__ out, int n)
{
    int w = blockIdx.x * 8 + (threadIdx.x >> 5);
    if (w >= n) return;
    int lane = threadIdx.x & 31;
    bool valid = (mask[(size_t)w * 4 + 3] == 0u);
    float4 o0, o1;
    if (valid) {
        const float4* xp = (const float4*)(x + (size_t)w * DIM);
        float4 v0 = xp[lane], v1 = xp[lane + 32];
        float s = v0.x + v0.y + v0.z + v0.w + v1.x + v1.y + v1.z + v1.w;
        float mu = warp_sum(s) * (1.f / DIM);
        float d0x = v0.x - mu, d0y = v0.y - mu, d0z = v0.z - mu, d0w = v0.w - mu;
        float d1x = v1.x - mu, d1y = v1.y - mu, d1z = v1.z - mu, d1w = v1.w - mu;
        float q = d0x*d0x + d0y*d0y + d0z*d0z + d0w*d0w + d1x*d1x + d1y*d1y + d1z*d1z + d1w*d1w;
        float inv = rsqrtf(warp_sum(q) * (1.f / DIM) + 1e-5f);
        const float4* gp = (const float4*)gam;
        const float4* bp = (const float4*)bet;
        float4 ga = gp[lane], gb = gp[lane + 32], ba = bp[lane], bb = bp[lane + 32];
        o0 = make_float4(d0x*inv*ga.x + ba.x, d0y*inv*ga.y + ba.y,
                         d0z*inv*ga.z + ba.z, d0w*inv*ga.w + ba.w);
        o1 = make_float4(d1x*inv*gb.x + bb.x, d1y*inv*gb.y + bb.y,
                         d1z*inv*gb.z + bb.z, d1w*inv*gb.w + bb.w);
    } else {
        const float4* op = (const float4*)(x0 + (size_t)w * DIM);
        o0 = op[lane]; o1 = op[lane + 32];
    }
    float4* dst = (float4*)(out + (size_t)w * DIM);
    dst[lane] = o0; dst[lane + 32] = o1;
}

// ---------------------------------------------------------------------------
// Bank shift + mask shift
// ---------------------------------------------------------------------------
__global__ __launch_bounds__(256)
void bank_k(const float* __restrict__ bank, const float* __restrict__ save,
            const float* __restrict__ scores, float* __restrict__ obank, int n)
{
    int t = blockIdx.x * blockDim.x + threadIdx.x;  // one float4 each
    int total = n * LMEM * (DIM / 4);
    if (t >= total) return;
    int nn = t >> 8;           // / (4*64)
    int r  = t & 255;
    int l  = r >> 6, c4 = r & 63;
    bool saved = scores[nn] > 0.f;
    float4 v;
    if (saved) {
        if (l < 3) v = ((const float4*)bank)[((size_t)nn * 4 + l + 1) * 64 + c4];
        else       v = ((const float4*)save)[(size_t)nn * 64 + c4];
    } else {
        v = ((const float4*)bank)[((size_t)nn * 4 + l) * 64 + c4];
    }
    ((float4*)obank)[t] = v;
}

__global__ __launch_bounds__(256)
void mask_k(const unsigned* __restrict__ mask, const float* __restrict__ scores,
            float* __restrict__ om, int n)
{
    int t = blockIdx.x * blockDim.x + threadIdx.x;
    if (t >= n) return;
    bool saved = scores[t] > 0.f;
    const unsigned* m = mask + (size_t)t * 4;
    float4 o;
    if (saved) o = make_float4(m[1] ? 1.f : 0.f, m[2] ? 1.f : 0.f, m[3] ? 1.f : 0.f, 0.f);
    else       o = make_float4(m[0] ? 1.f : 0.f, m[1] ? 1.f : 0.f, m[2] ? 1.f : 0.f, m[3] ? 1.f : 0.f);
    ((float4*)om)[t] = o;
}

// ---------------------------------------------------------------------------
// Launch
// ---------------------------------------------------------------------------
extern "C" void kernel_launch(void* const* d_in, const int* in_sizes, int n_in,
                              void* d_out, int out_size)
{
    const float*    x      = (const float*)d_in[0];
    const float*    scores = (const float*)d_in[1];
    const float*    bank   = (const float*)d_in[2];
    const unsigned* mask   = (const unsigned*)d_in[3];
    const float*    save_w = (const float*)d_in[4];
    const float*    save_b = (const float*)d_in[5];
    const float*    in_w   = (const float*)d_in[6];
    const float*    in_b   = (const float*)d_in[7];
    const float*    out_w  = (const float*)d_in[8];
    const float*    out_b  = (const float*)d_in[9];
    const float*    fc1_w  = (const float*)d_in[10];
    const float*    fc1_b  = (const float*)d_in[11];
    const float*    fc2_w  = (const float*)d_in[12];
    const float*    fc2_b  = (const float*)d_in[13];
    const float*    ln1_g  = (const float*)d_in[14];
    const float*    ln1_b  = (const float*)d_in[15];
    const float*    ln2_g  = (const float*)d_in[16];
    const float*    ln2_b  = (const float*)d_in[17];

    const int n = in_sizes[1];   // scores element count = number of tracks

    void* sp = nullptr;
    cudaGetSymbolAddress(&sp, g_scratch);
    unsigned char* base = (unsigned char*)sp;
    __nv_bfloat16* g_q   = (__nv_bfloat16*)(base + OFF_Q);
    __nv_bfloat16* g_kv  = (__nv_bfloat16*)(base + OFF_KV);
    __nv_bfloat16* g_ctx = (__nv_bfloat16*)(base + OFF_CTX);
    __nv_bfloat16* g_h   = (__nv_bfloat16*)(base + OFF_H);
    float*         g_y   = (float*)(base + OFF_Y);
    float*         g_e   = (float*)(base + OFF_E);
    float*         g_sv  = (float*)(base + OFF_SV);

    float* out_emb  = (float*)d_out;
    float* out_bank = out_emb + (size_t)n * DIM;
    float* out_mask = out_bank + (size_t)n * LMEM * DIM;

    const int mt   = (n + BM - 1) / BM;
    const int mt4  = (n * LMEM + BM - 1) / BM;
    const int wrp  = (n + 7) / 8;

    // 1) q = x @ Wq^T + bq  (bf16 out)
    gemm_k<float, 0, __nv_bfloat16><<<dim3(2, mt), 256>>>(
        x, in_w, in_b, nullptr, g_q, n, DIM);
    // 2) [k|v] = bank @ Wkv^T + bkv  (bf16 out, ldc=512)
    gemm_k<float, 0, __nv_bfloat16><<<dim3(4, mt4), 256>>>(
        bank, in_w + 256 * DIM, in_b + 256, nullptr, g_kv, n * LMEM, 512);
    // 3) attention -> ctx (bf16)
    attn_k<<<wrp, 256>>>(g_q, g_kv, mask, g_ctx, n);
    // 4) y = ctx @ Wo^T + bo + x
    gemm_k<__nv_bfloat16, 2, float><<<dim3(2, mt), 256>>>(
        g_ctx, out_w, out_b, x, g_y, n, DIM);
    // 5) e = LN1(y)
    ln_k<<<wrp, 256>>>(g_y, ln1_g, ln1_b, g_e, n);
    // 6) h = relu(e @ fc1^T + b1)  (bf16 out)
    gemm_k<float, 1, __nv_bfloat16><<<dim3(2, mt), 256>>>(
        g_e, fc1_w, fc1_b, nullptr, g_h, n, DIM);
    // 7) y2 = h @ fc2^T + b2 + e
    gemm_k<__nv_bfloat16, 2, float><<<dim3(2, mt), 256>>>(
        g_h, fc2_w, fc2_b, g_e, g_y, n, DIM);
    // 8) new_emb = valid ? LN2(y2) : x   -> straight into d_out
    ln2sel_k<<<wrp, 256>>>(g_y, ln2_g, ln2_b, mask, x, out_emb, n);
    // 9) save_embed = new_emb @ Wsave^T + bsave
    gemm_k<float, 0, float><<<dim3(2, mt), 256>>>(
        out_emb, save_w, save_b, nullptr, g_sv, n, DIM);
    // 10) bank shift, 11) mask shift
    bank_k<<<(n * 256 + 255) / 256, 256>>>(bank, g_sv, scores, out_bank, n);
    mask_k<<<(n + 255) / 256, 256>>>(mask, scores, out_mask, n);
}

// round 12
// speedup vs baseline: 1.2479x; 1.2479x over previous
#include <cuda_runtime.h>
#include <cuda_bf16.h>
#include <cstdint>
#include <type_traits>

// ---------------------------------------------------------------------------
// MemoryBank fused pipeline, GB300 sm_103a, round 12 (resubmission of R6 —
// broker timeouts before it could run).
// R5 evidence: GEMM mainloop latency-bound (tensor 21%, issue 19%, occ 24%,
// DRAM 27%). Fix: 2-stage cp.async double-buffered mainloop (1 bar/iter) +
// one-time weight pre-conversion to bf16 (B side becomes pure cp.async).
// ---------------------------------------------------------------------------

#define DIM 256            // D
#define LMEM 4             // memory bank length

// Scratch partition (bytes), all 16B aligned:
//  g_q   bf16 [N,256]        51,200,000
//  g_kv  bf16 [N*4,512]     409,600,000
//  g_ctx bf16 [N,256]        51,200,000
//  g_h   bf16 [N,256]        51,200,000
//  g_y   f32  [N,256]       102,400,000
//  g_e   f32  [N,256]       102,400,000
//  g_sv  f32  [N,256]       102,400,000
//  g_wb  bf16 [458752]           917,504   (all weights, bf16)
#define OFF_Q   0ull
#define OFF_KV  51200000ull
#define OFF_CTX 460800000ull
#define OFF_H   512000000ull
#define OFF_Y   563200000ull
#define OFF_E   665600000ull
#define OFF_SV  768000000ull
#define OFF_WB  870400000ull
#define SCRATCH_BYTES 871400000ull

// weight element offsets inside g_wb
#define WB_IN    0          // in_w   [768,256]
#define WB_OUT   196608     // out_w  [256,256]
#define WB_FC1   262144     // fc1_w  [256,256]
#define WB_FC2   327680     // fc2_w  [256,256]
#define WB_SAVE  393216     // save_w [256,256]
#define WB_TOTAL 458752

__device__ __align__(128) unsigned char g_scratch[SCRATCH_BYTES];

// ---------------------------------------------------------------------------
// cp.async helpers
// ---------------------------------------------------------------------------
__device__ __forceinline__ unsigned smem_u32(const void* p) {
    return (unsigned)__cvta_generic_to_shared(p);
}
__device__ __forceinline__ void cp16(unsigned dst, const void* src, int srcsize) {
    asm volatile("cp.async.cg.shared.global [%0], [%1], 16, %2;\n"
                 :: "r"(dst), "l"(src), "r"(srcsize));
}
__device__ __forceinline__ void cp_commit() {
    asm volatile("cp.async.commit_group;\n");
}
__device__ __forceinline__ void cp_wait0() {
    asm volatile("cp.async.wait_group 0;\n");
}

// ---------------------------------------------------------------------------
// bf16 m16n8k16 mma
// ---------------------------------------------------------------------------
__device__ __forceinline__ void mma_bf16(float (&d)[4], const unsigned (&a)[4],
                                         const unsigned (&b)[2]) {
    asm volatile(
        "mma.sync.aligned.m16n8k16.row.col.f32.bf16.bf16.f32 "
        "{%0,%1,%2,%3}, {%4,%5,%6,%7}, {%8,%9}, {%0,%1,%2,%3};\n"
        : "+f"(d[0]), "+f"(d[1]), "+f"(d[2]), "+f"(d[3])
        : "r"(a[0]), "r"(a[1]), "r"(a[2]), "r"(a[3]), "r"(b[0]), "r"(b[1]));
}

// ---------------------------------------------------------------------------
// One-time weight conversion fp32 -> bf16 into g_wb.
// Total 458752 elements = 1792 blocks x 256 threads exactly.
// ---------------------------------------------------------------------------
__global__ __launch_bounds__(256)
void cvtw_k(const float* __restrict__ in_w, const float* __restrict__ out_w,
            const float* __restrict__ fc1_w, const float* __restrict__ fc2_w,
            const float* __restrict__ save_w, __nv_bfloat16* __restrict__ dst)
{
    int i = blockIdx.x * 256 + threadIdx.x;
    const float* src; int off;
    if (i < WB_OUT)       { src = in_w;   off = i; }
    else if (i < WB_FC1)  { src = out_w;  off = i - WB_OUT; }
    else if (i < WB_FC2)  { src = fc1_w;  off = i - WB_FC1; }
    else if (i < WB_SAVE) { src = fc2_w;  off = i - WB_FC2; }
    else                  { src = save_w; off = i - WB_SAVE; }
    dst[i] = __float2bfloat16(src[off]);
}

// ---------------------------------------------------------------------------
// GEMM: C[M, ldc-slice] = A[M,256] @ Wb[Nc,256]^T + bias (+epilogue)
// BM=128, BN=128, BK=32; 256 threads; warp grid 2(m) x 4(n), warp tile 64x32.
// 2-stage double-buffered mainloop, one barrier per K-iter.
// Wb is bf16 (pre-converted) -> pure cp.async. A: cp.async if bf16,
// register-staged ldg/cvt/sts if fp32.
// EPI: 0 = bias, 1 = bias+relu, 2 = bias + residual (resid is [M,256] f32).
// ---------------------------------------------------------------------------
#define BM 128
#define BN 128
#define BK 32
#define SPAD 40   // smem row pitch (bf16 elems): conflict-free for frag loads

template <typename TA, int EPI, typename TO>
__global__ __launch_bounds__(256, 2)
void gemm_k(const TA* __restrict__ A, const __nv_bfloat16* __restrict__ Wb,
            const float* __restrict__ bias, const float* __restrict__ resid,
            TO* __restrict__ C, int M, int ldc)
{
    __shared__ __nv_bfloat16 sA[2][BM * SPAD];
    __shared__ __nv_bfloat16 sB[2][BN * SPAD];

    const int tid  = threadIdx.x;
    const int bm   = blockIdx.y * BM;
    const int bn   = blockIdx.x * BN;
    const int w    = tid >> 5, lane = tid & 31;
    const int wm   = w >> 2,  wn   = w & 3;
    const int g    = lane >> 2, t  = lane & 3;

    constexpr bool AF32 = std::is_same<TA, float>::value;

    float acc[4][4][4];
    #pragma unroll
    for (int i = 0; i < 4; i++)
        #pragma unroll
        for (int j = 0; j < 4; j++)
            #pragma unroll
            for (int k = 0; k < 4; k++) acc[i][j][k] = 0.f;

    // ---- stage loaders ----
    float4 ra[4];   // fp32-A register staging (live across mma when AF32)

    auto loadW = [&](int k0, int s) {
        #pragma unroll
        for (int i = 0; i < 2; i++) {
            int idx = tid + i * 256;
            int r = idx >> 2, c8 = (idx & 3) * 8;
            cp16(smem_u32(&sB[s][r * SPAD + c8]),
                 &Wb[(size_t)(bn + r) * DIM + k0 + c8], 16);
        }
    };
    auto loadA_cp = [&](int k0, int s) {
        #pragma unroll
        for (int i = 0; i < 2; i++) {
            int idx = tid + i * 256;
            int r = idx >> 2, c8 = (idx & 3) * 8;
            int rr = (bm + r < M) ? (bm + r) : (M - 1);   // keep addr valid
            cp16(smem_u32(&sA[s][r * SPAD + c8]),
                 &A[(size_t)rr * DIM + k0 + c8], (bm + r < M) ? 16 : 0);
        }
    };
    auto ldgA = [&](int k0) {
        #pragma unroll
        for (int i = 0; i < 4; i++) {
            int idx = tid + i * 256;
            int r = idx >> 3, c4 = (idx & 7) * 4;
            ra[i] = (bm + r < M)
                ? *(const float4*)&A[(size_t)(bm + r) * DIM + k0 + c4]
                : make_float4(0.f, 0.f, 0.f, 0.f);
        }
    };
    auto stsA = [&](int s) {
        #pragma unroll
        for (int i = 0; i < 4; i++) {
            int idx = tid + i * 256;
            int r = idx >> 3, c4 = (idx & 7) * 4;
            __nv_bfloat162* dst = (__nv_bfloat162*)&sA[s][r * SPAD + c4];
            dst[0] = __floats2bfloat162_rn(ra[i].x, ra[i].y);
            dst[1] = __floats2bfloat162_rn(ra[i].z, ra[i].w);
        }
    };

    // ---- prologue: fill stage 0 ----
    if constexpr (AF32) { ldgA(0); } else { loadA_cp(0, 0); }
    loadW(0, 0);
    cp_commit();
    if constexpr (AF32) stsA(0);
    cp_wait0();
    __syncthreads();

    // ---- mainloop: 8 K-iters, one barrier each ----
    #pragma unroll
    for (int k0i = 0; k0i < 8; k0i++) {
        const int cur = k0i & 1, nxt = cur ^ 1;

        // issue next-stage loads early (stage nxt last read in iter k0i-1,
        // whose end-of-iter barrier all warps have passed)
        if (k0i < 7) {
            if constexpr (AF32) ldgA((k0i + 1) * BK);
            else                loadA_cp((k0i + 1) * BK, nxt);
            loadW((k0i + 1) * BK, nxt);
            cp_commit();
        }

        // MMA on current stage
        #pragma unroll
        for (int km = 0; km < 2; km++) {
            const int kc = km * 16;
            unsigned af[4][4], bf[4][2];
            #pragma unroll
            for (int im = 0; im < 4; im++) {
                int r = wm * 64 + im * 16 + g;
                af[im][0] = *(const unsigned*)&sA[cur][r * SPAD + kc + 2 * t];
                af[im][1] = *(const unsigned*)&sA[cur][(r + 8) * SPAD + kc + 2 * t];
                af[im][2] = *(const unsigned*)&sA[cur][r * SPAD + kc + 8 + 2 * t];
                af[im][3] = *(const unsigned*)&sA[cur][(r + 8) * SPAD + kc + 8 + 2 * t];
            }
            #pragma unroll
            for (int jn = 0; jn < 4; jn++) {
                int nc = wn * 32 + jn * 8 + g;
                bf[jn][0] = *(const unsigned*)&sB[cur][nc * SPAD + kc + 2 * t];
                bf[jn][1] = *(const unsigned*)&sB[cur][nc * SPAD + kc + 8 + 2 * t];
            }
            #pragma unroll
            for (int im = 0; im < 4; im++)
                #pragma unroll
                for (int jn = 0; jn < 4; jn++)
                    mma_bf16(acc[im][jn], af[im], bf[jn]);
        }

        if (k0i < 7) {
            if constexpr (AF32) stsA(nxt);   // ldg latency hidden by mma above
            cp_wait0();
            __syncthreads();
        }
    }

    // ---- epilogue ----
    #pragma unroll
    for (int im = 0; im < 4; im++) {
        int rbase = bm + wm * 64 + im * 16 + g;
        #pragma unroll
        for (int jn = 0; jn < 4; jn++) {
            int c0 = bn + wn * 32 + jn * 8 + 2 * t;
            float b0 = bias[c0], b1 = bias[c0 + 1];
            #pragma unroll
            for (int half = 0; half < 2; half++) {
                int r = rbase + half * 8;
                if (r >= M) continue;
                float x0 = acc[im][jn][half * 2 + 0] + b0;
                float x1 = acc[im][jn][half * 2 + 1] + b1;
                if (EPI == 1) { x0 = fmaxf(x0, 0.f); x1 = fmaxf(x1, 0.f); }
                if (EPI == 2) {
                    const float* rp = resid + (size_t)r * DIM + c0;
                    x0 += rp[0]; x1 += rp[1];
                }
                if constexpr (std::is_same<TO, float>::value) {
                    *(float2*)&C[(size_t)r * ldc + c0] = make_float2(x0, x1);
                } else {
                    *(__nv_bfloat162*)&C[(size_t)r * ldc + c0] =
                        __floats2bfloat162_rn(x0, x1);
                }
            }
        }
    }
}

// ---------------------------------------------------------------------------
// Attention: one warp per track. lane -> (h = lane/4, l = lane%4).
// logits over L=4 slots per head, softmax within 4-lane groups.
// ---------------------------------------------------------------------------
__global__ __launch_bounds__(256)
void attn_k(const __nv_bfloat16* __restrict__ q, const __nv_bfloat16* __restrict__ kv,
            const unsigned* __restrict__ mask, __nv_bfloat16* __restrict__ ctx, int n)
{
    int w = blockIdx.x * 8 + (threadIdx.x >> 5);
    if (w >= n) return;
    int lane = threadIdx.x & 31;
    int h = lane >> 2, l = lane & 3;

    bool valid = (mask[(size_t)w * 4 + 3] == 0u);
    bool pad   = valid && (mask[(size_t)w * 4 + l] != 0u);

    const __nv_bfloat162* qp = (const __nv_bfloat162*)(q + (size_t)w * DIM + h * 32);
    const __nv_bfloat162* kp = (const __nv_bfloat162*)(kv + ((size_t)w * 4 + l) * 512 + h * 32);
    float dot = 0.f;
    #pragma unroll
    for (int i = 0; i < 16; i++) {
        float2 qf = __bfloat1622float2(qp[i]);
        float2 kf = __bfloat1622float2(kp[i]);
        dot += qf.x * kf.x + qf.y * kf.y;
    }
    float logit = dot * 0.17677669529663687f;   // 1/sqrt(32)
    if (pad) logit = -1e9f;

    float m = logit;
    m = fmaxf(m, __shfl_xor_sync(0xffffffffu, m, 1));
    m = fmaxf(m, __shfl_xor_sync(0xffffffffu, m, 2));
    float p = __expf(logit - m);
    float s = p;
    s += __shfl_xor_sync(0xffffffffu, s, 1);
    s += __shfl_xor_sync(0xffffffffu, s, 2);
    float attn = p / s;

    const __nv_bfloat162* vp = (const __nv_bfloat162*)(kv + ((size_t)w * 4 + l) * 512 + 256 + h * 32);
    float c[32];
    #pragma unroll
    for (int i = 0; i < 16; i++) {
        float2 vf = __bfloat1622float2(vp[i]);
        c[2 * i]     = attn * vf.x;
        c[2 * i + 1] = attn * vf.y;
    }
    #pragma unroll
    for (int i = 0; i < 32; i++) {
        c[i] += __shfl_xor_sync(0xffffffffu, c[i], 1);
        c[i] += __shfl_xor_sync(0xffffffffu, c[i], 2);
    }
    // lane with slot l writes dims [l*8, l*8+8)
    __nv_bfloat162* op = (__nv_bfloat162*)(ctx + (size_t)w * DIM + h * 32 + l * 8);
    #pragma unroll
    for (int j = 0; j < 4; j++)
        op[j] = __floats2bfloat162_rn(c[l * 8 + 2 * j], c[l * 8 + 2 * j + 1]);
}

// ---------------------------------------------------------------------------
// LayerNorm helpers (one warp per row of 256)
// ---------------------------------------------------------------------------
__device__ __forceinline__ float warp_sum(float v) {
    #pragma unroll
    for (int o = 16; o; o >>= 1) v += __shfl_xor_sync(0xffffffffu, v, o);
    return v;
}

__global__ __launch_bounds__(256)
void ln_k(const float* __restrict__ x, const float* __restrict__ gam,
          const float* __restrict__ bet, float* __restrict__ out, int n)
{
    int w = blockIdx.x * 8 + (threadIdx.x >> 5);
    if (w >= n) return;
    int lane = threadIdx.x & 31;
    const float4* xp = (const float4*)(x + (size_t)w * DIM);
    float4 v0 = xp[lane], v1 = xp[lane + 32];
    float s = v0.x + v0.y + v0.z + v0.w + v1.x + v1.y + v1.z + v1.w;
    float mu = warp_sum(s) * (1.f / DIM);
    float d0x = v0.x - mu, d0y = v0.y - mu, d0z = v0.z - mu, d0w = v0.w - mu;
    float d1x = v1.x - mu, d1y = v1.y - mu, d1z = v1.z - mu, d1w = v1.w - mu;
    float q = d0x*d0x + d0y*d0y + d0z*d0z + d0w*d0w + d1x*d1x + d1y*d1y + d1z*d1z + d1w*d1w;
    float inv = rsqrtf(warp_sum(q) * (1.f / DIM) + 1e-5f);
    const float4* gp = (const float4*)gam;
    const float4* bp = (const float4*)bet;
    float4 ga = gp[lane], gb = gp[lane + 32], ba = bp[lane], bb = bp[lane + 32];
    float4 o0 = make_float4(d0x*inv*ga.x + ba.x, d0y*inv*ga.y + ba.y,
                            d0z*inv*ga.z + ba.z, d0w*inv*ga.w + ba.w);
    float4 o1 = make_float4(d1x*inv*gb.x + bb.x, d1y*inv*gb.y + bb.y,
                            d1z*inv*gb.z + bb.z, d1w*inv*gb.w + bb.w);
    float4* dst = (float4*)(out + (size_t)w * DIM);
    dst[lane] = o0; dst[lane + 32] = o1;
}

__global__ __launch_bounds__(256)
void ln2sel_k(const float* __restrict__ x, const float* __restrict__ gam,
              const float* __restrict__ bet, const unsigned* __restrict__ mask,
              const float* __restrict__ x0, float* __restrict__ out, int n)
{
    int w = blockIdx.x * 8 + (threadIdx.x >> 5);
    if (w >= n) return;
    int lane = threadIdx.x & 31;
    bool valid = (mask[(size_t)w * 4 + 3] == 0u);
    float4 o0, o1;
    if (valid) {
        const float4* xp = (const float4*)(x + (size_t)w * DIM);
        float4 v0 = xp[lane], v1 = xp[lane + 32];
        float s = v0.x + v0.y + v0.z + v0.w + v1.x + v1.y + v1.z + v1.w;
        float mu = warp_sum(s) * (1.f / DIM);
        float d0x = v0.x - mu, d0y = v0.y - mu, d0z = v0.z - mu, d0w = v0.w - mu;
        float d1x = v1.x - mu, d1y = v1.y - mu, d1z = v1.z - mu, d1w = v1.w - mu;
        float q = d0x*d0x + d0y*d0y + d0z*d0z + d0w*d0w + d1x*d1x + d1y*d1y + d1z*d1z + d1w*d1w;
        float inv = rsqrtf(warp_sum(q) * (1.f / DIM) + 1e-5f);
        const float4* gp = (const float4*)gam;
        const float4* bp = (const float4*)bet;
        float4 ga = gp[lane], gb = gp[lane + 32], ba = bp[lane], bb = bp[lane + 32];
        o0 = make_float4(d0x*inv*ga.x + ba.x, d0y*inv*ga.y + ba.y,
                         d0z*inv*ga.z + ba.z, d0w*inv*ga.w + ba.w);
        o1 = make_float4(d1x*inv*gb.x + bb.x, d1y*inv*gb.y + bb.y,
                         d1z*inv*gb.z + bb.z, d1w*inv*gb.w + bb.w);
    } else {
        const float4* op = (const float4*)(x0 + (size_t)w * DIM);
        o0 = op[lane]; o1 = op[lane + 32];
    }
    float4* dst = (float4*)(out + (size_t)w * DIM);
    dst[lane] = o0; dst[lane + 32] = o1;
}

// ---------------------------------------------------------------------------
// Bank shift + mask shift
// ---------------------------------------------------------------------------
__global__ __launch_bounds__(256)
void bank_k(const float* __restrict__ bank, const float* __restrict__ save,
            const float* __restrict__ scores, float* __restrict__ obank, int n)
{
    int t = blockIdx.x * blockDim.x + threadIdx.x;  // one float4 each
    int total = n * LMEM * (DIM / 4);
    if (t >= total) return;
    int nn = t >> 8;           // / (4*64)
    int r  = t & 255;
    int l  = r >> 6, c4 = r & 63;
    bool saved = scores[nn] > 0.f;
    float4 v;
    if (saved) {
        if (l < 3) v = ((const float4*)bank)[((size_t)nn * 4 + l + 1) * 64 + c4];
        else       v = ((const float4*)save)[(size_t)nn * 64 + c4];
    } else {
        v = ((const float4*)bank)[((size_t)nn * 4 + l) * 64 + c4];
    }
    ((float4*)obank)[t] = v;
}

__global__ __launch_bounds__(256)
void mask_k(const unsigned* __restrict__ mask, const float* __restrict__ scores,
            float* __restrict__ om, int n)
{
    int t = blockIdx.x * blockDim.x + threadIdx.x;
    if (t >= n) return;
    bool saved = scores[t] > 0.f;
    const unsigned* m = mask + (size_t)t * 4;
    float4 o;
    if (saved) o = make_float4(m[1] ? 1.f : 0.f, m[2] ? 1.f : 0.f, m[3] ? 1.f : 0.f, 0.f);
    else       o = make_float4(m[0] ? 1.f : 0.f, m[1] ? 1.f : 0.f, m[2] ? 1.f : 0.f, m[3] ? 1.f : 0.f);
    ((float4*)om)[t] = o;
}

// ---------------------------------------------------------------------------
// Launch
// ---------------------------------------------------------------------------
extern "C" void kernel_launch(void* const* d_in, const int* in_sizes, int n_in,
                              void* d_out, int out_size)
{
    const float*    x      = (const float*)d_in[0];
    const float*    scores = (const float*)d_in[1];
    const float*    bank   = (const float*)d_in[2];
    const unsigned* mask   = (const unsigned*)d_in[3];
    const float*    save_w = (const float*)d_in[4];
    const float*    save_b = (const float*)d_in[5];
    const float*    in_w   = (const float*)d_in[6];
    const float*    in_b   = (const float*)d_in[7];
    const float*    out_w  = (const float*)d_in[8];
    const float*    out_b  = (const float*)d_in[9];
    const float*    fc1_w  = (const float*)d_in[10];
    const float*    fc1_b  = (const float*)d_in[11];
    const float*    fc2_w  = (const float*)d_in[12];
    const float*    fc2_b  = (const float*)d_in[13];
    const float*    ln1_g  = (const float*)d_in[14];
    const float*    ln1_b  = (const float*)d_in[15];
    const float*    ln2_g  = (const float*)d_in[16];
    const float*    ln2_b  = (const float*)d_in[17];

    const int n = in_sizes[1];   // scores element count = number of tracks

    void* sp = nullptr;
    cudaGetSymbolAddress(&sp, g_scratch);
    unsigned char* base = (unsigned char*)sp;
    __nv_bfloat16* g_q   = (__nv_bfloat16*)(base + OFF_Q);
    __nv_bfloat16* g_kv  = (__nv_bfloat16*)(base + OFF_KV);
    __nv_bfloat16* g_ctx = (__nv_bfloat16*)(base + OFF_CTX);
    __nv_bfloat16* g_h   = (__nv_bfloat16*)(base + OFF_H);
    float*         g_y   = (float*)(base + OFF_Y);
    float*         g_e   = (float*)(base + OFF_E);
    float*         g_sv  = (float*)(base + OFF_SV);
    __nv_bfloat16* g_wb  = (__nv_bfloat16*)(base + OFF_WB);

    float* out_emb  = (float*)d_out;
    float* out_bank = out_emb + (size_t)n * DIM;
    float* out_mask = out_bank + (size_t)n * LMEM * DIM;

    const int mt   = (n + BM - 1) / BM;
    const int mt4  = (n * LMEM + BM - 1) / BM;
    const int wrp  = (n + 7) / 8;

    // 0) weights -> bf16 (once per replay; deterministic)
    cvtw_k<<<WB_TOTAL / 256, 256>>>(in_w, out_w, fc1_w, fc2_w, save_w, g_wb);

    // 1) q = x @ Wq^T + bq  (bf16 out)
    gemm_k<float, 0, __nv_bfloat16><<<dim3(2, mt), 256>>>(
        x, g_wb + WB_IN, in_b, nullptr, g_q, n, DIM);
    // 2) [k|v] = bank @ Wkv^T + bkv  (bf16 out, ldc=512)
    gemm_k<float, 0, __nv_bfloat16><<<dim3(4, mt4), 256>>>(
        bank, g_wb + WB_IN + 256 * DIM, in_b + 256, nullptr, g_kv, n * LMEM, 512);
    // 3) attention -> ctx (bf16)
    attn_k<<<wrp, 256>>>(g_q, g_kv, mask, g_ctx, n);
    // 4) y = ctx @ Wo^T + bo + x
    gemm_k<__nv_bfloat16, 2, float><<<dim3(2, mt), 256>>>(
        g_ctx, g_wb + WB_OUT, out_b, x, g_y, n, DIM);
    // 5) e = LN1(y)
    ln_k<<<wrp, 256>>>(g_y, ln1_g, ln1_b, g_e, n);
    // 6) h = relu(e @ fc1^T + b1)  (bf16 out)
    gemm_k<float, 1, __nv_bfloat16><<<dim3(2, mt), 256>>>(
        g_e, g_wb + WB_FC1, fc1_b, nullptr, g_h, n, DIM);
    // 7) y2 = h @ fc2^T + b2 + e
    gemm_k<__nv_bfloat16, 2, float><<<dim3(2, mt), 256>>>(
        g_h, g_wb + WB_FC2, fc2_b, g_e, g_y, n, DIM);
    // 8) new_emb = valid ? LN2(y2) : x   -> straight into d_out
    ln2sel_k<<<wrp, 256>>>(g_y, ln2_g, ln2_b, mask, x, out_emb, n);
    // 9) save_embed = new_emb @ Wsave^T + bsave
    gemm_k<float, 0, float><<<dim3(2, mt), 256>>>(
        out_emb, g_wb + WB_SAVE, save_b, nullptr, g_sv, n, DIM);
    // 10) bank shift, 11) mask shift
    bank_k<<<(n * 256 + 255) / 256, 256>>>(bank, g_sv, scores, out_bank, n);
    mask_k<<<(n + 255) / 256, 256>>>(mask, scores, out_mask, n);
}

// round 16
// speedup vs baseline: 1.4165x; 1.1351x over previous
#include <cuda_runtime.h>
#include <cuda_bf16.h>
#include <cstdint>
#include <type_traits>

// ---------------------------------------------------------------------------
// MemoryBank fused pipeline, GB300 sm_103a, round 16 (resubmission of R13 —
// broker timeouts before it could run).
// R12: pipelined GEMM WIN 1548->1241us. Top launch: attn_k 222.8us,
// L1tex-saturated (95.5%) from 48 scalar LDG.32 + 68 SHFL per thread.
// Fix: uint4 loads + lane remap in output phase (8 shfl total, 16B stores).
// ---------------------------------------------------------------------------

#define DIM 256            // D
#define LMEM 4             // memory bank length

// Scratch partition (bytes), all 16B aligned:
#define OFF_Q   0ull
#define OFF_KV  51200000ull
#define OFF_CTX 460800000ull
#define OFF_H   512000000ull
#define OFF_Y   563200000ull
#define OFF_E   665600000ull
#define OFF_SV  768000000ull
#define OFF_WB  870400000ull
#define SCRATCH_BYTES 871400000ull

// weight element offsets inside g_wb
#define WB_IN    0          // in_w   [768,256]
#define WB_OUT   196608     // out_w  [256,256]
#define WB_FC1   262144     // fc1_w  [256,256]
#define WB_FC2   327680     // fc2_w  [256,256]
#define WB_SAVE  393216     // save_w [256,256]
#define WB_TOTAL 458752

__device__ __align__(128) unsigned char g_scratch[SCRATCH_BYTES];

// ---------------------------------------------------------------------------
// cp.async helpers
// ---------------------------------------------------------------------------
__device__ __forceinline__ unsigned smem_u32(const void* p) {
    return (unsigned)__cvta_generic_to_shared(p);
}
__device__ __forceinline__ void cp16(unsigned dst, const void* src, int srcsize) {
    asm volatile("cp.async.cg.shared.global [%0], [%1], 16, %2;\n"
                 :: "r"(dst), "l"(src), "r"(srcsize));
}
__device__ __forceinline__ void cp_commit() {
    asm volatile("cp.async.commit_group;\n");
}
__device__ __forceinline__ void cp_wait0() {
    asm volatile("cp.async.wait_group 0;\n");
}

// ---------------------------------------------------------------------------
// bf16 m16n8k16 mma
// ---------------------------------------------------------------------------
__device__ __forceinline__ void mma_bf16(float (&d)[4], const unsigned (&a)[4],
                                         const unsigned (&b)[2]) {
    asm volatile(
        "mma.sync.aligned.m16n8k16.row.col.f32.bf16.bf16.f32 "
        "{%0,%1,%2,%3}, {%4,%5,%6,%7}, {%8,%9}, {%0,%1,%2,%3};\n"
        : "+f"(d[0]), "+f"(d[1]), "+f"(d[2]), "+f"(d[3])
        : "r"(a[0]), "r"(a[1]), "r"(a[2]), "r"(a[3]), "r"(b[0]), "r"(b[1]));
}

// ---------------------------------------------------------------------------
// One-time weight conversion fp32 -> bf16 into g_wb.
// ---------------------------------------------------------------------------
__global__ __launch_bounds__(256)
void cvtw_k(const float* __restrict__ in_w, const float* __restrict__ out_w,
            const float* __restrict__ fc1_w, const float* __restrict__ fc2_w,
            const float* __restrict__ save_w, __nv_bfloat16* __restrict__ dst)
{
    int i = blockIdx.x * 256 + threadIdx.x;
    const float* src; int off;
    if (i < WB_OUT)       { src = in_w;   off = i; }
    else if (i < WB_FC1)  { src = out_w;  off = i - WB_OUT; }
    else if (i < WB_FC2)  { src = fc1_w;  off = i - WB_FC1; }
    else if (i < WB_SAVE) { src = fc2_w;  off = i - WB_FC2; }
    else                  { src = save_w; off = i - WB_SAVE; }
    dst[i] = __float2bfloat16(src[off]);
}

// ---------------------------------------------------------------------------
// GEMM (unchanged from R12 green build): 2-stage cp.async double-buffered.
// ---------------------------------------------------------------------------
#define BM 128
#define BN 128
#define BK 32
#define SPAD 40

template <typename TA, int EPI, typename TO>
__global__ __launch_bounds__(256, 2)
void gemm_k(const TA* __restrict__ A, const __nv_bfloat16* __restrict__ Wb,
            const float* __restrict__ bias, const float* __restrict__ resid,
            TO* __restrict__ C, int M, int ldc)
{
    __shared__ __nv_bfloat16 sA[2][BM * SPAD];
    __shared__ __nv_bfloat16 sB[2][BN * SPAD];

    const int tid  = threadIdx.x;
    const int bm   = blockIdx.y * BM;
    const int bn   = blockIdx.x * BN;
    const int w    = tid >> 5, lane = tid & 31;
    const int wm   = w >> 2,  wn   = w & 3;
    const int g    = lane >> 2, t  = lane & 3;

    constexpr bool AF32 = std::is_same<TA, float>::value;

    float acc[4][4][4];
    #pragma unroll
    for (int i = 0; i < 4; i++)
        #pragma unroll
        for (int j = 0; j < 4; j++)
            #pragma unroll
            for (int k = 0; k < 4; k++) acc[i][j][k] = 0.f;

    float4 ra[4];

    auto loadW = [&](int k0, int s) {
        #pragma unroll
        for (int i = 0; i < 2; i++) {
            int idx = tid + i * 256;
            int r = idx >> 2, c8 = (idx & 3) * 8;
            cp16(smem_u32(&sB[s][r * SPAD + c8]),
                 &Wb[(size_t)(bn + r) * DIM + k0 + c8], 16);
        }
    };
    auto loadA_cp = [&](int k0, int s) {
        #pragma unroll
        for (int i = 0; i < 2; i++) {
            int idx = tid + i * 256;
            int r = idx >> 2, c8 = (idx & 3) * 8;
            int rr = (bm + r < M) ? (bm + r) : (M - 1);
            cp16(smem_u32(&sA[s][r * SPAD + c8]),
                 &A[(size_t)rr * DIM + k0 + c8], (bm + r < M) ? 16 : 0);
        }
    };
    auto ldgA = [&](int k0) {
        #pragma unroll
        for (int i = 0; i < 4; i++) {
            int idx = tid + i * 256;
            int r = idx >> 3, c4 = (idx & 7) * 4;
            ra[i] = (bm + r < M)
                ? *(const float4*)&A[(size_t)(bm + r) * DIM + k0 + c4]
                : make_float4(0.f, 0.f, 0.f, 0.f);
        }
    };
    auto stsA = [&](int s) {
        #pragma unroll
        for (int i = 0; i < 4; i++) {
            int idx = tid + i * 256;
            int r = idx >> 3, c4 = (idx & 7) * 4;
            __nv_bfloat162* dst = (__nv_bfloat162*)&sA[s][r * SPAD + c4];
            dst[0] = __floats2bfloat162_rn(ra[i].x, ra[i].y);
            dst[1] = __floats2bfloat162_rn(ra[i].z, ra[i].w);
        }
    };

    if constexpr (AF32) { ldgA(0); } else { loadA_cp(0, 0); }
    loadW(0, 0);
    cp_commit();
    if constexpr (AF32) stsA(0);
    cp_wait0();
    __syncthreads();

    #pragma unroll
    for (int k0i = 0; k0i < 8; k0i++) {
        const int cur = k0i & 1, nxt = cur ^ 1;

        if (k0i < 7) {
            if constexpr (AF32) ldgA((k0i + 1) * BK);
            else                loadA_cp((k0i + 1) * BK, nxt);
            loadW((k0i + 1) * BK, nxt);
            cp_commit();
        }

        #pragma unroll
        for (int km = 0; km < 2; km++) {
            const int kc = km * 16;
            unsigned af[4][4], bf[4][2];
            #pragma unroll
            for (int im = 0; im < 4; im++) {
                int r = wm * 64 + im * 16 + g;
                af[im][0] = *(const unsigned*)&sA[cur][r * SPAD + kc + 2 * t];
                af[im][1] = *(const unsigned*)&sA[cur][(r + 8) * SPAD + kc + 2 * t];
                af[im][2] = *(const unsigned*)&sA[cur][r * SPAD + kc + 8 + 2 * t];
                af[im][3] = *(const unsigned*)&sA[cur][(r + 8) * SPAD + kc + 8 + 2 * t];
            }
            #pragma unroll
            for (int jn = 0; jn < 4; jn++) {
                int nc = wn * 32 + jn * 8 + g;
                bf[jn][0] = *(const unsigned*)&sB[cur][nc * SPAD + kc + 2 * t];
                bf[jn][1] = *(const unsigned*)&sB[cur][nc * SPAD + kc + 8 + 2 * t];
            }
            #pragma unroll
            for (int im = 0; im < 4; im++)
                #pragma unroll
                for (int jn = 0; jn < 4; jn++)
                    mma_bf16(acc[im][jn], af[im], bf[jn]);
        }

        if (k0i < 7) {
            if constexpr (AF32) stsA(nxt);
            cp_wait0();
            __syncthreads();
        }
    }

    #pragma unroll
    for (int im = 0; im < 4; im++) {
        int rbase = bm + wm * 64 + im * 16 + g;
        #pragma unroll
        for (int jn = 0; jn < 4; jn++) {
            int c0 = bn + wn * 32 + jn * 8 + 2 * t;
            float b0 = bias[c0], b1 = bias[c0 + 1];
            #pragma unroll
            for (int half = 0; half < 2; half++) {
                int r = rbase + half * 8;
                if (r >= M) continue;
                float x0 = acc[im][jn][half * 2 + 0] + b0;
                float x1 = acc[im][jn][half * 2 + 1] + b1;
                if (EPI == 1) { x0 = fmaxf(x0, 0.f); x1 = fmaxf(x1, 0.f); }
                if (EPI == 2) {
                    const float* rp = resid + (size_t)r * DIM + c0;
                    x0 += rp[0]; x1 += rp[1];
                }
                if constexpr (std::is_same<TO, float>::value) {
                    *(float2*)&C[(size_t)r * ldc + c0] = make_float2(x0, x1);
                } else {
                    *(__nv_bfloat162*)&C[(size_t)r * ldc + c0] =
                        __floats2bfloat162_rn(x0, x1);
                }
            }
        }
    }
}

// ---------------------------------------------------------------------------
// Attention v2: one warp per track, vectorized.
// Phase 1: lane (h = lane/4, l = lane%4) computes logit[h][l] via uint4 loads,
//          softmax within the 4-lane head group (4 shfls).
// Phase 2: lane remapped to (h, dim-chunk c = lane%4): gathers the 4 attn
//          weights of its head group (4 shfls), accumulates 8 output dims
//          from 4 x 16B v-loads, writes one 16B store.
// ---------------------------------------------------------------------------
__device__ __forceinline__ float dot8bf(uint4 a, uint4 b) {
    const __nv_bfloat162* a2 = (const __nv_bfloat162*)&a;
    const __nv_bfloat162* b2 = (const __nv_bfloat162*)&b;
    float d = 0.f;
    #pragma unroll
    for (int j = 0; j < 4; j++) {
        float2 af = __bfloat1622float2(a2[j]);
        float2 bf = __bfloat1622float2(b2[j]);
        d += af.x * bf.x + af.y * bf.y;
    }
    return d;
}

__global__ __launch_bounds__(256)
void attn_k(const __nv_bfloat16* __restrict__ q, const __nv_bfloat16* __restrict__ kv,
            const unsigned* __restrict__ mask, __nv_bfloat16* __restrict__ ctx, int n)
{
    int w = blockIdx.x * 8 + (threadIdx.x >> 5);
    if (w >= n) return;
    int lane = threadIdx.x & 31;
    int h = lane >> 2, l = lane & 3;

    // mask (16B broadcast load; same addr across warp)
    uint4 mv = *(const uint4*)(mask + (size_t)w * 4);
    bool valid = (mv.w == 0u);
    unsigned ml = (l == 0) ? mv.x : (l == 1) ? mv.y : (l == 2) ? mv.z : mv.w;
    bool pad = valid && (ml != 0u);

    // ---- phase 1: logit over head-dim 32 (64B = 4 x uint4) ----
    const uint4* qp = (const uint4*)(q + (size_t)w * DIM + h * 32);
    const uint4* kp = (const uint4*)(kv + ((size_t)w * 4 + l) * 512 + h * 32);
    float dot = 0.f;
    #pragma unroll
    for (int i = 0; i < 4; i++)
        dot += dot8bf(qp[i], kp[i]);

    float logit = dot * 0.17677669529663687f;   // 1/sqrt(32)
    if (pad) logit = -1e9f;

    float m = logit;
    m = fmaxf(m, __shfl_xor_sync(0xffffffffu, m, 1));
    m = fmaxf(m, __shfl_xor_sync(0xffffffffu, m, 2));
    float p = __expf(logit - m);
    float s = p;
    s += __shfl_xor_sync(0xffffffffu, s, 1);
    s += __shfl_xor_sync(0xffffffffu, s, 2);
    float attn = p / s;

    // ---- phase 2: lane (h, c=l) computes output dims [h*32+c*8, +8) ----
    int gbase = lane & ~3;   // first lane of this head group
    float a0 = __shfl_sync(0xffffffffu, attn, gbase + 0);
    float a1 = __shfl_sync(0xffffffffu, attn, gbase + 1);
    float a2 = __shfl_sync(0xffffffffu, attn, gbase + 2);
    float a3 = __shfl_sync(0xffffffffu, attn, gbase + 3);

    const __nv_bfloat16* vbase = kv + (size_t)w * 4 * 512 + 256 + h * 32 + l * 8;
    float acc[8];
    #pragma unroll
    for (int d = 0; d < 8; d++) acc[d] = 0.f;
    const float aw[4] = {a0, a1, a2, a3};
    #pragma unroll
    for (int j = 0; j < 4; j++) {
        uint4 vv = *(const uint4*)(vbase + (size_t)j * 512);
        const __nv_bfloat162* v2 = (const __nv_bfloat162*)&vv;
        #pragma unroll
        for (int d2 = 0; d2 < 4; d2++) {
            float2 vf = __bfloat1622float2(v2[d2]);
            acc[2 * d2]     += aw[j] * vf.x;
            acc[2 * d2 + 1] += aw[j] * vf.y;
        }
    }

    uint4 ov;
    __nv_bfloat162* o2 = (__nv_bfloat162*)&ov;
    #pragma unroll
    for (int d2 = 0; d2 < 4; d2++)
        o2[d2] = __floats2bfloat162_rn(acc[2 * d2], acc[2 * d2 + 1]);
    *(uint4*)(ctx + (size_t)w * DIM + h * 32 + l * 8) = ov;
}

// ---------------------------------------------------------------------------
// LayerNorm helpers (one warp per row of 256)
// ---------------------------------------------------------------------------
__device__ __forceinline__ float warp_sum(float v) {
    #pragma unroll
    for (int o = 16; o; o >>= 1) v += __shfl_xor_sync(0xffffffffu, v, o);
    return v;
}

__global__ __launch_bounds__(256)
void ln_k(const float* __restrict__ x, const float* __restrict__ gam,
          const float* __restrict__ bet, float* __restrict__ out, int n)
{
    int w = blockIdx.x * 8 + (threadIdx.x >> 5);
    if (w >= n) return;
    int lane = threadIdx.x & 31;
    const float4* xp = (const float4*)(x + (size_t)w * DIM);
    float4 v0 = xp[lane], v1 = xp[lane + 32];
    float s = v0.x + v0.y + v0.z + v0.w + v1.x + v1.y + v1.z + v1.w;
    float mu = warp_sum(s) * (1.f / DIM);
    float d0x = v0.x - mu, d0y = v0.y - mu, d0z = v0.z - mu, d0w = v0.w - mu;
    float d1x = v1.x - mu, d1y = v1.y - mu, d1z = v1.z - mu, d1w = v1.w - mu;
    float q = d0x*d0x + d0y*d0y + d0z*d0z + d0w*d0w + d1x*d1x + d1y*d1y + d1z*d1z + d1w*d1w;
    float inv = rsqrtf(warp_sum(q) * (1.f / DIM) + 1e-5f);
    const float4* gp = (const float4*)gam;
    const float4* bp = (const float4*)bet;
    float4 ga = gp[lane], gb = gp[lane + 32], ba = bp[lane], bb = bp[lane + 32];
    float4 o0 = make_float4(d0x*inv*ga.x + ba.x, d0y*inv*ga.y + ba.y,
                            d0z*inv*ga.z + ba.z, d0w*inv*ga.w + ba.w);
    float4 o1 = make_float4(d1x*inv*gb.x + bb.x, d1y*inv*gb.y + bb.y,
                            d1z*inv*gb.z + bb.z, d1w*inv*gb.w + bb.w);
    float4* dst = (float4*)(out + (size_t)w * DIM);
    dst[lane] = o0; dst[lane + 32] = o1;
}

__global__ __launch_bounds__(256)
void ln2sel_k(const float* __restrict__ x, const float* __restrict__ gam,
              const float* __restrict__ bet, const unsigned* __restrict__ mask,
              const float* __restrict__ x0, float* __restrict__ out, int n)
{
    int w = blockIdx.x * 8 + (threadIdx.x >> 5);
    if (w >= n) return;
    int lane = threadIdx.x & 31;
    bool valid = (mask[(size_t)w * 4 + 3] == 0u);
    float4 o0, o1;
    if (valid) {
        const float4* xp = (const float4*)(x + (size_t)w * DIM);
        float4 v0 = xp[lane], v1 = xp[lane + 32];
        float s = v0.x + v0.y + v0.z + v0.w + v1.x + v1.y + v1.z + v1.w;
        float mu = warp_sum(s) * (1.f / DIM);
        float d0x = v0.x - mu, d0y = v0.y - mu, d0z = v0.z - mu, d0w = v0.w - mu;
        float d1x = v1.x - mu, d1y = v1.y - mu, d1z = v1.z - mu, d1w = v1.w - mu;
        float q = d0x*d0x + d0y*d0y + d0z*d0z + d0w*d0w + d1x*d1x + d1y*d1y + d1z*d1z + d1w*d1w;
        float inv = rsqrtf(warp_sum(q) * (1.f / DIM) + 1e-5f);
        const float4* gp = (const float4*)gam;
        const float4* bp = (const float4*)bet;
        float4 ga = gp[lane], gb = gp[lane + 32], ba = bp[lane], bb = bp[lane + 32];
        o0 = make_float4(d0x*inv*ga.x + ba.x, d0y*inv*ga.y + ba.y,
                         d0z*inv*ga.z + ba.z, d0w*inv*ga.w + ba.w);
        o1 = make_float4(d1x*inv*gb.x + bb.x, d1y*inv*gb.y + bb.y,
                         d1z*inv*gb.z + bb.z, d1w*inv*gb.w + bb.w);
    } else {
        const float4* op = (const float4*)(x0 + (size_t)w * DIM);
        o0 = op[lane]; o1 = op[lane + 32];
    }
    float4* dst = (float4*)(out + (size_t)w * DIM);
    dst[lane] = o0; dst[lane + 32] = o1;
}

// ---------------------------------------------------------------------------
// Bank shift + mask shift
// ---------------------------------------------------------------------------
__global__ __launch_bounds__(256)
void bank_k(const float* __restrict__ bank, const float* __restrict__ save,
            const float* __restrict__ scores, float* __restrict__ obank, int n)
{
    int t = blockIdx.x * blockDim.x + threadIdx.x;  // one float4 each
    int total = n * LMEM * (DIM / 4);
    if (t >= total) return;
    int nn = t >> 8;
    int r  = t & 255;
    int l  = r >> 6, c4 = r & 63;
    bool saved = scores[nn] > 0.f;
    float4 v;
    if (saved) {
        if (l < 3) v = ((const float4*)bank)[((size_t)nn * 4 + l + 1) * 64 + c4];
        else       v = ((const float4*)save)[(size_t)nn * 64 + c4];
    } else {
        v = ((const float4*)bank)[((size_t)nn * 4 + l) * 64 + c4];
    }
    ((float4*)obank)[t] = v;
}

__global__ __launch_bounds__(256)
void mask_k(const unsigned* __restrict__ mask, const float* __restrict__ scores,
            float* __restrict__ om, int n)
{
    int t = blockIdx.x * blockDim.x + threadIdx.x;
    if (t >= n) return;
    bool saved = scores[t] > 0.f;
    const unsigned* m = mask + (size_t)t * 4;
    float4 o;
    if (saved) o = make_float4(m[1] ? 1.f : 0.f, m[2] ? 1.f : 0.f, m[3] ? 1.f : 0.f, 0.f);
    else       o = make_float4(m[0] ? 1.f : 0.f, m[1] ? 1.f : 0.f, m[2] ? 1.f : 0.f, m[3] ? 1.f : 0.f);
    ((float4*)om)[t] = o;
}

// ---------------------------------------------------------------------------
// Launch
// ---------------------------------------------------------------------------
extern "C" void kernel_launch(void* const* d_in, const int* in_sizes, int n_in,
                              void* d_out, int out_size)
{
    const float*    x      = (const float*)d_in[0];
    const float*    scores = (const float*)d_in[1];
    const float*    bank   = (const float*)d_in[2];
    const unsigned* mask   = (const unsigned*)d_in[3];
    const float*    save_w = (const float*)d_in[4];
    const float*    save_b = (const float*)d_in[5];
    const float*    in_w   = (const float*)d_in[6];
    const float*    in_b   = (const float*)d_in[7];
    const float*    out_w  = (const float*)d_in[8];
    const float*    out_b  = (const float*)d_in[9];
    const float*    fc1_w  = (const float*)d_in[10];
    const float*    fc1_b  = (const float*)d_in[11];
    const float*    fc2_w  = (const float*)d_in[12];
    const float*    fc2_b  = (const float*)d_in[13];
    const float*    ln1_g  = (const float*)d_in[14];
    const float*    ln1_b  = (const float*)d_in[15];
    const float*    ln2_g  = (const float*)d_in[16];
    const float*    ln2_b  = (const float*)d_in[17];

    const int n = in_sizes[1];

    void* sp = nullptr;
    cudaGetSymbolAddress(&sp, g_scratch);
    unsigned char* base = (unsigned char*)sp;
    __nv_bfloat16* g_q   = (__nv_bfloat16*)(base + OFF_Q);
    __nv_bfloat16* g_kv  = (__nv_bfloat16*)(base + OFF_KV);
    __nv_bfloat16* g_ctx = (__nv_bfloat16*)(base + OFF_CTX);
    __nv_bfloat16* g_h   = (__nv_bfloat16*)(base + OFF_H);
    float*         g_y   = (float*)(base + OFF_Y);
    float*         g_e   = (float*)(base + OFF_E);
    float*         g_sv  = (float*)(base + OFF_SV);
    __nv_bfloat16* g_wb  = (__nv_bfloat16*)(base + OFF_WB);

    float* out_emb  = (float*)d_out;
    float* out_bank = out_emb + (size_t)n * DIM;
    float* out_mask = out_bank + (size_t)n * LMEM * DIM;

    const int mt   = (n + BM - 1) / BM;
    const int mt4  = (n * LMEM + BM - 1) / BM;
    const int wrp  = (n + 7) / 8;

    // 0) weights -> bf16 (once per replay; deterministic)
    cvtw_k<<<WB_TOTAL / 256, 256>>>(in_w, out_w, fc1_w, fc2_w, save_w, g_wb);

    // 1) q = x @ Wq^T + bq  (bf16 out)
    gemm_k<float, 0, __nv_bfloat16><<<dim3(2, mt), 256>>>(
        x, g_wb + WB_IN, in_b, nullptr, g_q, n, DIM);
    // 2) [k|v] = bank @ Wkv^T + bkv  (bf16 out, ldc=512)
    gemm_k<float, 0, __nv_bfloat16><<<dim3(4, mt4), 256>>>(
        bank, g_wb + WB_IN + 256 * DIM, in_b + 256, nullptr, g_kv, n * LMEM, 512);
    // 3) attention -> ctx (bf16)
    attn_k<<<wrp, 256>>>(g_q, g_kv, mask, g_ctx, n);
    // 4) y = ctx @ Wo^T + bo + x
    gemm_k<__nv_bfloat16, 2, float><<<dim3(2, mt), 256>>>(
        g_ctx, g_wb + WB_OUT, out_b, x, g_y, n, DIM);
    // 5) e = LN1(y)
    ln_k<<<wrp, 256>>>(g_y, ln1_g, ln1_b, g_e, n);
    // 6) h = relu(e @ fc1^T + b1)  (bf16 out)
    gemm_k<float, 1, __nv_bfloat16><<<dim3(2, mt), 256>>>(
        g_e, g_wb + WB_FC1, fc1_b, nullptr, g_h, n, DIM);
    // 7) y2 = h @ fc2^T + b2 + e
    gemm_k<__nv_bfloat16, 2, float><<<dim3(2, mt), 256>>>(
        g_h, g_wb + WB_FC2, fc2_b, g_e, g_y, n, DIM);
    // 8) new_emb = valid ? LN2(y2) : x   -> straight into d_out
    ln2sel_k<<<wrp, 256>>>(g_y, ln2_g, ln2_b, mask, x, out_emb, n);
    // 9) save_embed = new_emb @ Wsave^T + bsave
    gemm_k<float, 0, float><<<dim3(2, mt), 256>>>(
        out_emb, g_wb + WB_SAVE, save_b, nullptr, g_sv, n, DIM);
    // 10) bank shift, 11) mask shift
    bank_k<<<(n * 256 + 255) / 256, 256>>>(bank, g_sv, scores, out_bank, n);
    mask_k<<<(n + 255) / 256, 256>>>(mask, scores, out_mask, n);
}